// round 1
// baseline (speedup 1.0000x reference)
#include <cuda_runtime.h>

// ---------------------------------------------------------------------------
// QFCModel: avgpool(6x6) -> linear(16->4) -> 4-qubit/3-layer VQC -> linear(4->4)
//           -> BatchNorm1d (training mode, batch stats)
//
// Kernel 1 (qfc_main): one thread per sample. Pool + encode + full circuit
//   simulation in registers (16 complex amplitudes) + classifier head.
//   Writes raw pre-BN out[B,4].
// Kernel 2 (bn_stats): one block, deterministic tree reduction of per-channel
//   sum / sumsq; writes fused scale/shift into __device__ globals.
// Kernel 3 (bn_apply): out = out*scale[c] + shift[c], vectorized float4.
// ---------------------------------------------------------------------------

__device__ float g_scale[4];
__device__ float g_shift[4];

// Apply 2x2 complex gate U to qubit with stride S on a 16-amplitude state.
template <int S>
__device__ __forceinline__ void apply1q(float re[16], float im[16],
                                        float u00r, float u00i,
                                        float u01r, float u01i,
                                        float u10r, float u10i,
                                        float u11r, float u11i) {
#pragma unroll
    for (int a = 0; a < 16; ++a) {
        if (a & S) continue;
        const int b = a + S;
        const float x0r = re[a], x0i = im[a];
        const float x1r = re[b], x1i = im[b];
        re[a] = u00r * x0r - u00i * x0i + u01r * x1r - u01i * x1i;
        im[a] = u00r * x0i + u00i * x0r + u01r * x1i + u01i * x1r;
        re[b] = u10r * x0r - u10i * x0i + u11r * x1r - u11i * x1i;
        im[b] = u10r * x0i + u10i * x0r + u11r * x1i + u11i * x1r;
    }
}

// CNOT: swap amplitudes with control bit (stride SC) set, over target (stride ST).
template <int SC, int ST>
__device__ __forceinline__ void apply_cnot(float re[16], float im[16]) {
#pragma unroll
    for (int a = 0; a < 16; ++a) {
        if ((a & SC) && !(a & ST)) {
            const int b = a + ST;
            float t;
            t = re[a]; re[a] = re[b]; re[b] = t;
            t = im[a]; im[a] = im[b]; im[b] = t;
        }
    }
}

__global__ __launch_bounds__(256) void qfc_main(
    const float* __restrict__ x,        // [B,1,28,28]
    const float* __restrict__ enc_w,    // [4,16]
    const float* __restrict__ enc_b,    // [4]
    const float* __restrict__ qparams,  // [3,4,3]
    const float* __restrict__ cls_w,    // [4,4]
    const float* __restrict__ cls_b,    // [4]
    float* __restrict__ out,            // [B,4]
    int B)
{
    // --- Precompute the 12 Rot gates (fixed per launch) into shared memory ---
    // Rot(phi,theta,omega) = RZ(omega) RY(theta) RZ(phi):
    //   U00 = cos(t/2) e^{-i(phi+omega)/2}
    //   U01 = -sin(t/2) e^{+i(phi-omega)/2}
    //   U10 =  sin(t/2) e^{-i(phi-omega)/2}
    //   U11 = cos(t/2) e^{+i(phi+omega)/2}
    __shared__ float sg[12][8];
    const int tid = threadIdx.x;
    if (tid < 12) {
        const float phi = qparams[tid * 3 + 0];
        const float th  = qparams[tid * 3 + 1];
        const float om  = qparams[tid * 3 + 2];
        float sp, cp, sm, cm, st, ct;
        sincosf(0.5f * (phi + om), &sp, &cp);
        sincosf(0.5f * (phi - om), &sm, &cm);
        sincosf(0.5f * th, &st, &ct);
        sg[tid][0] =  ct * cp;  sg[tid][1] = -ct * sp;   // U00
        sg[tid][2] = -st * cm;  sg[tid][3] = -st * sm;   // U01
        sg[tid][4] =  st * cm;  sg[tid][5] = -st * sm;   // U10
        sg[tid][6] =  ct * cp;  sg[tid][7] =  ct * sp;   // U11
    }
    __syncthreads();

    const int b = blockIdx.x * blockDim.x + tid;
    if (b >= B) return;

    // --- avg_pool2d(6) on the top-left 24x24 ---
    float pooled[16];
#pragma unroll
    for (int f = 0; f < 16; ++f) pooled[f] = 0.f;

    // sample base: b*784 floats = b*3136 bytes (16B aligned); row stride 112B (16B aligned)
    const float4* xb = reinterpret_cast<const float4*>(x + (size_t)b * 784);
#pragma unroll
    for (int r = 0; r < 24; ++r) {
        const int pr = r / 6;
        float rowv[24];
#pragma unroll
        for (int q = 0; q < 6; ++q) {
            const float4 v = __ldg(xb + r * 7 + q);
            rowv[q * 4 + 0] = v.x; rowv[q * 4 + 1] = v.y;
            rowv[q * 4 + 2] = v.z; rowv[q * 4 + 3] = v.w;
        }
#pragma unroll
        for (int c = 0; c < 24; ++c) pooled[pr * 4 + c / 6] += rowv[c];
    }
#pragma unroll
    for (int f = 0; f < 16; ++f) pooled[f] *= (1.0f / 36.0f);

    // --- encoder: z = pooled @ enc_w^T + enc_b ---
    float z[4];
#pragma unroll
    for (int w = 0; w < 4; ++w) {
        float acc = __ldg(enc_b + w);
#pragma unroll
        for (int f = 0; f < 16; ++f) acc += pooled[f] * __ldg(enc_w + w * 16 + f);
        z[w] = acc;
    }

    // --- initial state: RX(z_w) layer applied to |0000>.
    // amp(idx) = prod_w (bit? sin(z/2) : cos(z/2)) * (-i)^popcount(idx)
    float cw[4], sw[4];
#pragma unroll
    for (int w = 0; w < 4; ++w) __sincosf(0.5f * z[w], &sw[w], &cw[w]);

    float re[16], im[16];
#pragma unroll
    for (int idx = 0; idx < 16; ++idx) {
        const float p = (idx & 8 ? sw[0] : cw[0]) *
                        (idx & 4 ? sw[1] : cw[1]) *
                        (idx & 2 ? sw[2] : cw[2]) *
                        (idx & 1 ? sw[3] : cw[3]);
        const int m = __popc(idx) & 3;   // (-i)^m phase
        re[idx] = (m == 0) ? p : ((m == 2) ? -p : 0.f);
        im[idx] = (m == 1) ? -p : ((m == 3) ? p : 0.f);
    }

    // --- 3 variational layers: Rot on every wire, then CNOT ladder ---
    // qubit w acts on bit (3-w): stride 8 >> w
#pragma unroll
    for (int layer = 0; layer < 3; ++layer) {
        const float* g;
        g = sg[layer * 4 + 0];
        apply1q<8>(re, im, g[0], g[1], g[2], g[3], g[4], g[5], g[6], g[7]);
        g = sg[layer * 4 + 1];
        apply1q<4>(re, im, g[0], g[1], g[2], g[3], g[4], g[5], g[6], g[7]);
        g = sg[layer * 4 + 2];
        apply1q<2>(re, im, g[0], g[1], g[2], g[3], g[4], g[5], g[6], g[7]);
        g = sg[layer * 4 + 3];
        apply1q<1>(re, im, g[0], g[1], g[2], g[3], g[4], g[5], g[6], g[7]);
        apply_cnot<8, 4>(re, im);
        apply_cnot<4, 2>(re, im);
        apply_cnot<2, 1>(re, im);
    }

    // --- <Z_w> expectation values ---
    float prob[16];
#pragma unroll
    for (int i = 0; i < 16; ++i) prob[i] = re[i] * re[i] + im[i] * im[i];

    float ev[4];
#pragma unroll
    for (int w = 0; w < 4; ++w) {
        const int s = 8 >> w;
        float e = 0.f;
#pragma unroll
        for (int i = 0; i < 16; ++i) e += (i & s) ? -prob[i] : prob[i];
        ev[w] = e;
    }

    // --- classifier head ---
    float4 o;
    float* op = &o.x;
#pragma unroll
    for (int oo = 0; oo < 4; ++oo) {
        float acc = __ldg(cls_b + oo);
#pragma unroll
        for (int w = 0; w < 4; ++w) acc += ev[w] * __ldg(cls_w + oo * 4 + w);
        op[oo] = acc;
    }
    reinterpret_cast<float4*>(out)[b] = o;
}

// --- deterministic batch statistics (single block, tree reduce keeps channel
//     congruence because every stride is a multiple of 4) ---
__global__ __launch_bounds__(1024) void bn_stats(
    const float* __restrict__ out,
    const float* __restrict__ gamma,
    const float* __restrict__ beta,
    int B)
{
    __shared__ float ssum[1024];
    __shared__ float ssq[1024];
    const int tid = threadIdx.x;
    const int n = B * 4;

    float s0 = 0.f, q0 = 0.f, s1 = 0.f, q1 = 0.f;
    for (int i = tid; i < n; i += 2048) {
        const float v = out[i];
        s0 += v; q0 = fmaf(v, v, q0);
        const int j = i + 1024;
        if (j < n) {
            const float u = out[j];
            s1 += u; q1 = fmaf(u, u, q1);
        }
    }
    ssum[tid] = s0 + s1;
    ssq[tid]  = q0 + q1;
    __syncthreads();

#pragma unroll
    for (int off = 512; off >= 4; off >>= 1) {
        if (tid < off) {
            ssum[tid] += ssum[tid + off];
            ssq[tid]  += ssq[tid + off];
        }
        __syncthreads();
    }

    if (tid < 4) {
        const float invB = 1.0f / (float)B;
        const float mu  = ssum[tid] * invB;
        const float var = ssq[tid] * invB - mu * mu;
        const float sc  = gamma[tid] * rsqrtf(var + 1e-5f);
        g_scale[tid] = sc;
        g_shift[tid] = beta[tid] - mu * sc;
    }
}

__global__ __launch_bounds__(256) void bn_apply(float* __restrict__ out, int B)
{
    const int i = blockIdx.x * blockDim.x + threadIdx.x;
    if (i < B) {
        float4 v = reinterpret_cast<float4*>(out)[i];
        v.x = v.x * g_scale[0] + g_shift[0];
        v.y = v.y * g_scale[1] + g_shift[1];
        v.z = v.z * g_scale[2] + g_shift[2];
        v.w = v.w * g_scale[3] + g_shift[3];
        reinterpret_cast<float4*>(out)[i] = v;
    }
}

extern "C" void kernel_launch(void* const* d_in, const int* in_sizes, int n_in,
                              void* d_out, int out_size)
{
    const float* x        = (const float*)d_in[0];
    const float* enc_w    = (const float*)d_in[1];
    const float* enc_b    = (const float*)d_in[2];
    const float* qparams  = (const float*)d_in[3];
    const float* cls_w    = (const float*)d_in[4];
    const float* cls_b    = (const float*)d_in[5];
    const float* bn_gamma = (const float*)d_in[6];
    const float* bn_beta  = (const float*)d_in[7];
    float* out = (float*)d_out;

    const int B = in_sizes[0] / 784;

    qfc_main<<<(B + 255) / 256, 256>>>(x, enc_w, enc_b, qparams, cls_w, cls_b, out, B);
    bn_stats<<<1, 1024>>>(out, bn_gamma, bn_beta, B);
    bn_apply<<<(B + 255) / 256, 256>>>(out, B);
}

// round 2
// speedup vs baseline: 1.0685x; 1.0685x over previous
#include <cuda_runtime.h>

// ---------------------------------------------------------------------------
// QFCModel: avgpool(6x6) -> linear(16->4) -> 4-qubit/3-layer VQC -> linear(4->4)
//           -> BatchNorm1d (training mode, batch stats)
//
// R2: 4 threads per sample (occupancy 12%->~44%); BN partial sums fused into
//     the main kernel (deterministic shuffle+smem tree per block).
// ---------------------------------------------------------------------------

__device__ float g_scale[4];
__device__ float g_shift[4];
__device__ float g_partial[2048 * 8];   // per-block {sum[4], sumsq[4]}

// Apply 2x2 complex gate U to qubit with stride S on a 16-amplitude state.
template <int S>
__device__ __forceinline__ void apply1q(float re[16], float im[16],
                                        float u00r, float u00i,
                                        float u01r, float u01i,
                                        float u10r, float u10i,
                                        float u11r, float u11i) {
#pragma unroll
    for (int a = 0; a < 16; ++a) {
        if (a & S) continue;
        const int b = a + S;
        const float x0r = re[a], x0i = im[a];
        const float x1r = re[b], x1i = im[b];
        re[a] = u00r * x0r - u00i * x0i + u01r * x1r - u01i * x1i;
        im[a] = u00r * x0i + u00i * x0r + u01r * x1i + u01i * x1r;
        re[b] = u10r * x0r - u10i * x0i + u11r * x1r - u11i * x1i;
        im[b] = u10r * x0i + u10i * x0r + u11r * x1i + u11i * x1r;
    }
}

template <int SC, int ST>
__device__ __forceinline__ void apply_cnot(float re[16], float im[16]) {
#pragma unroll
    for (int a = 0; a < 16; ++a) {
        if ((a & SC) && !(a & ST)) {
            const int b = a + ST;
            float t;
            t = re[a]; re[a] = re[b]; re[b] = t;
            t = im[a]; im[a] = im[b]; im[b] = t;
        }
    }
}

__global__ __launch_bounds__(256) void qfc_main(
    const float* __restrict__ x,        // [B,1,28,28]
    const float* __restrict__ enc_w,    // [4,16]
    const float* __restrict__ enc_b,    // [4]
    const float* __restrict__ qparams,  // [3,4,3]
    const float* __restrict__ cls_w,    // [4,4]
    const float* __restrict__ cls_b,    // [4]
    float* __restrict__ out,            // [B,4]
    int B)
{
    // --- Precompute the 12 Rot gates into shared memory ---
    __shared__ float sg[12][8];
    __shared__ float sred[8][8];
    const int tid = threadIdx.x;
    if (tid < 12) {
        const float phi = qparams[tid * 3 + 0];
        const float th  = qparams[tid * 3 + 1];
        const float om  = qparams[tid * 3 + 2];
        float sp, cp, sm, cm, st, ct;
        sincosf(0.5f * (phi + om), &sp, &cp);
        sincosf(0.5f * (phi - om), &sm, &cm);
        sincosf(0.5f * th, &st, &ct);
        sg[tid][0] =  ct * cp;  sg[tid][1] = -ct * sp;   // U00
        sg[tid][2] = -st * cm;  sg[tid][3] = -st * sm;   // U01
        sg[tid][4] =  st * cm;  sg[tid][5] = -st * sm;   // U10
        sg[tid][6] =  ct * cp;  sg[tid][7] =  ct * sp;   // U11
    }
    __syncthreads();

    const int gid = blockIdx.x * 256 + tid;
    const int b = gid >> 2;       // sample
    const int t = gid & 3;        // pooled-row owner (rows 6t..6t+5)
    const bool valid = (b < B);

    float4 o = make_float4(0.f, 0.f, 0.f, 0.f);

    if (valid) {
        // --- this thread's pooled row: column sums over rows 6t..6t+5 ---
        const float4* xb = reinterpret_cast<const float4*>(x + (size_t)b * 784);
        const int rbase = t * 6;
        float cs0 = 0.f, cs1 = 0.f, cs2 = 0.f, cs3 = 0.f;
#pragma unroll
        for (int r = 0; r < 6; ++r) {
            const float4* rp = xb + (rbase + r) * 7;
            const float4 a0 = __ldg(rp + 0);
            const float4 a1 = __ldg(rp + 1);
            const float4 a2 = __ldg(rp + 2);
            const float4 a3 = __ldg(rp + 3);
            const float4 a4 = __ldg(rp + 4);
            const float4 a5 = __ldg(rp + 5);
            cs0 += a0.x + a0.y + a0.z + a0.w + a1.x + a1.y;             // cols 0-5
            cs1 += a1.z + a1.w + a2.x + a2.y + a2.z + a2.w;             // cols 6-11
            cs2 += a3.x + a3.y + a3.z + a3.w + a4.x + a4.y;             // cols 12-17
            cs3 += a4.z + a4.w + a5.x + a5.y + a5.z + a5.w;             // cols 18-23
        }

        // --- partial encoder dot: features t*4 .. t*4+3 ---
        float pz[4];
#pragma unroll
        for (int w = 0; w < 4; ++w) {
            const float* wr = enc_w + w * 16 + t * 4;
            pz[w] = cs0 * __ldg(wr + 0) + cs1 * __ldg(wr + 1)
                  + cs2 * __ldg(wr + 2) + cs3 * __ldg(wr + 3);
        }
        // reduce across the 4-lane sample group
#pragma unroll
        for (int w = 0; w < 4; ++w) {
            pz[w] += __shfl_xor_sync(0xffffffffu, pz[w], 1);
            pz[w] += __shfl_xor_sync(0xffffffffu, pz[w], 2);
        }
        float z[4];
#pragma unroll
        for (int w = 0; w < 4; ++w) z[w] = pz[w] * (1.0f / 36.0f) + __ldg(enc_b + w);

        // --- initial state: RX layer on |0000> in closed form ---
        float cw[4], sw[4];
#pragma unroll
        for (int w = 0; w < 4; ++w) __sincosf(0.5f * z[w], &sw[w], &cw[w]);

        float re[16], im[16];
#pragma unroll
        for (int idx = 0; idx < 16; ++idx) {
            const float p = (idx & 8 ? sw[0] : cw[0]) *
                            (idx & 4 ? sw[1] : cw[1]) *
                            (idx & 2 ? sw[2] : cw[2]) *
                            (idx & 1 ? sw[3] : cw[3]);
            const int m = __popc(idx) & 3;
            re[idx] = (m == 0) ? p : ((m == 2) ? -p : 0.f);
            im[idx] = (m == 1) ? -p : ((m == 3) ? p : 0.f);
        }

        // --- variational layers (all 4 lanes compute redundantly) ---
#pragma unroll
        for (int layer = 0; layer < 3; ++layer) {
            const float* g;
            g = sg[layer * 4 + 0];
            apply1q<8>(re, im, g[0], g[1], g[2], g[3], g[4], g[5], g[6], g[7]);
            g = sg[layer * 4 + 1];
            apply1q<4>(re, im, g[0], g[1], g[2], g[3], g[4], g[5], g[6], g[7]);
            g = sg[layer * 4 + 2];
            apply1q<2>(re, im, g[0], g[1], g[2], g[3], g[4], g[5], g[6], g[7]);
            g = sg[layer * 4 + 3];
            apply1q<1>(re, im, g[0], g[1], g[2], g[3], g[4], g[5], g[6], g[7]);
            apply_cnot<8, 4>(re, im);
            apply_cnot<4, 2>(re, im);
            apply_cnot<2, 1>(re, im);
        }

        // --- <Z_w> and classifier head ---
        float prob[16];
#pragma unroll
        for (int i = 0; i < 16; ++i) prob[i] = re[i] * re[i] + im[i] * im[i];

        float ev[4];
#pragma unroll
        for (int w = 0; w < 4; ++w) {
            const int s = 8 >> w;
            float e = 0.f;
#pragma unroll
            for (int i = 0; i < 16; ++i) e += (i & s) ? -prob[i] : prob[i];
            ev[w] = e;
        }

        float* op = &o.x;
#pragma unroll
        for (int oo = 0; oo < 4; ++oo) {
            float acc = __ldg(cls_b + oo);
#pragma unroll
            for (int w = 0; w < 4; ++w) acc += ev[w] * __ldg(cls_w + oo * 4 + w);
            op[oo] = acc;
        }
        if (t == 0) reinterpret_cast<float4*>(out)[b] = o;
    }

    // --- fused BN partials: each sample counted once per warp reduction ---
    // lanes: bits[1:0]=t (identical o within group), bits[4:2]=sample slot.
    float vals[8];
    const float inv4 = 0.25f;   // each sample appears in 4 lanes -> scale by 1/4
    vals[0] = o.x * inv4; vals[1] = o.y * inv4;
    vals[2] = o.z * inv4; vals[3] = o.w * inv4;
    vals[4] = o.x * o.x * inv4; vals[5] = o.y * o.y * inv4;
    vals[6] = o.z * o.z * inv4; vals[7] = o.w * o.w * inv4;
    // full warp reduction (each sample's 4 identical copies scaled by 1/4)
#pragma unroll
    for (int j = 0; j < 8; ++j) {
#pragma unroll
        for (int m = 1; m < 32; m <<= 1)
            vals[j] += __shfl_xor_sync(0xffffffffu, vals[j], m);
    }
    const int warpid = tid >> 5;
    if ((tid & 31) == 0) {
#pragma unroll
        for (int j = 0; j < 8; ++j) sred[warpid][j] = vals[j];
    }
    __syncthreads();
    if (tid < 8) {
        float s = 0.f;
#pragma unroll
        for (int k = 0; k < 8; ++k) s += sred[k][tid];
        g_partial[blockIdx.x * 8 + tid] = s;
    }
}

// --- finalize: reduce per-block partials, compute fused scale/shift ---
__global__ __launch_bounds__(64) void bn_finalize(
    const float* __restrict__ gamma,
    const float* __restrict__ beta,
    int nblocks, int B)
{
    __shared__ float sm[8][8];
    const int tid = threadIdx.x;
    const int j = tid & 7;       // channel/stat index
    const int g = tid >> 3;      // stripe
    float s = 0.f;
    for (int k = g; k < nblocks; k += 8) s += g_partial[k * 8 + j];
    sm[g][j] = s;
    __syncthreads();
    if (tid < 4) {
        float sum = 0.f, sq = 0.f;
#pragma unroll
        for (int k = 0; k < 8; ++k) { sum += sm[k][tid]; sq += sm[k][tid + 4]; }
        const float invB = 1.0f / (float)B;
        const float mu  = sum * invB;
        const float var = sq * invB - mu * mu;
        const float sc  = gamma[tid] * rsqrtf(var + 1e-5f);
        g_scale[tid] = sc;
        g_shift[tid] = beta[tid] - mu * sc;
    }
}

__global__ __launch_bounds__(256) void bn_apply(float* __restrict__ out, int B)
{
    const int i = blockIdx.x * blockDim.x + threadIdx.x;
    if (i < B) {
        float4 v = reinterpret_cast<float4*>(out)[i];
        v.x = v.x * g_scale[0] + g_shift[0];
        v.y = v.y * g_scale[1] + g_shift[1];
        v.z = v.z * g_scale[2] + g_shift[2];
        v.w = v.w * g_scale[3] + g_shift[3];
        reinterpret_cast<float4*>(out)[i] = v;
    }
}

extern "C" void kernel_launch(void* const* d_in, const int* in_sizes, int n_in,
                              void* d_out, int out_size)
{
    const float* x        = (const float*)d_in[0];
    const float* enc_w    = (const float*)d_in[1];
    const float* enc_b    = (const float*)d_in[2];
    const float* qparams  = (const float*)d_in[3];
    const float* cls_w    = (const float*)d_in[4];
    const float* cls_b    = (const float*)d_in[5];
    const float* bn_gamma = (const float*)d_in[6];
    const float* bn_beta  = (const float*)d_in[7];
    float* out = (float*)d_out;

    const int B = in_sizes[0] / 784;
    const int nblocks = (B * 4 + 255) / 256;

    qfc_main<<<nblocks, 256>>>(x, enc_w, enc_b, qparams, cls_w, cls_b, out, B);
    bn_finalize<<<1, 64>>>(bn_gamma, bn_beta, nblocks, B);
    bn_apply<<<(B + 255) / 256, 256>>>(out, B);
}